// round 4
// baseline (speedup 1.0000x reference)
#include <cuda_runtime.h>
#include <math.h>

#define TOK 32768          // B * H * W tokens
#define CC 256             // dim
#define HEADS 8
#define HID 1024
#define NWIN 512           // B * nW windows
#define DEPTH 2

// ---------------- scratch (static device globals; no runtime alloc) ----------------
__device__ float g_hw [TOK * CC];        // LN1 + shifted window partition
__device__ float g_qkv[TOK * 3 * CC];    // qkv activations
__device__ float g_att[TOK * CC];        // attention output (window-token order)
__device__ float g_ln [TOK * CC];        // LN2 output
__device__ float g_mid[TOK * HID];       // MLP hidden

// window-token row t  ->  source/dest pixel row (shift applied mod 64)
__device__ __forceinline__ int pix_row(int t, int shift) {
    int win = t >> 6, tok = t & 63;
    int b = win >> 6, wi = win & 63;
    int rp = ((wi >> 3) << 3) + (tok >> 3);
    int cp = ((wi & 7) << 3) + (tok & 7);
    int r = (rp + shift) & 63;
    int c = (cp + shift) & 63;
    return (b << 12) + (r << 6) + c;
}

__device__ __forceinline__ float gelu_exact(float x) {
    return 0.5f * x * (1.0f + erff(x * 0.7071067811865476f));
}

// ---------------- LayerNorm (optionally fused shift + window partition) ----------------
// one block (256 threads) per output row
__global__ __launch_bounds__(256) void ln_kernel(
    const float* __restrict__ in, const float* __restrict__ g,
    const float* __restrict__ b, float* __restrict__ out,
    int permute, int shift)
{
    int row = blockIdx.x;
    int src = permute ? pix_row(row, shift) : row;
    int ch = threadIdx.x;
    float v = in[(size_t)src * CC + ch];

    float s = v, s2 = v * v;
    #pragma unroll
    for (int o = 16; o; o >>= 1) {
        s  += __shfl_xor_sync(0xffffffffu, s,  o);
        s2 += __shfl_xor_sync(0xffffffffu, s2, o);
    }
    __shared__ float ws[8], ws2[8];
    int w = ch >> 5, l = ch & 31;
    if (l == 0) { ws[w] = s; ws2[w] = s2; }
    __syncthreads();
    float ts = 0.f, ts2 = 0.f;
    #pragma unroll
    for (int i = 0; i < 8; i++) { ts += ws[i]; ts2 += ws2[i]; }
    float mu  = ts * (1.0f / CC);
    float var = ts2 * (1.0f / CC) - mu * mu;
    float inv = rsqrtf(var + 1e-5f);
    out[(size_t)row * CC + ch] = (v - mu) * inv * g[ch] + b[ch];
}

// ---------------- tiled fp32 GEMM: out[M,N] = A[M,K] @ W[K,N] + bias, fused epilogues ----
// EPI 0: store   EPI 1: GELU+store   EPI 2: scatter (window-reverse+unshift) + residual into xbuf
// EPI 3: residual add into xbuf (identity row map)
template<int EPI>
__global__ __launch_bounds__(256) void gemm_kernel(
    const float* __restrict__ A, const float* __restrict__ W,
    const float* __restrict__ bias, float* __restrict__ out,
    int M, int N, int K, float* __restrict__ xbuf, int shift)
{
    __shared__ float As[16][128];
    __shared__ float Bs[16][64];
    const int tid = threadIdx.x;
    const int bm = blockIdx.y << 7;
    const int bn = blockIdx.x << 6;

    const int trow = (tid >> 4) << 3;   // 0..120
    const int tcol = (tid & 15) << 2;   // 0..60

    const int arow = tid >> 2;          // 0..63
    const int acol = (tid & 3) << 2;    // 0,4,8,12
    const int brow = tid >> 4;          // 0..15
    const int bcol = (tid & 15) << 2;   // 0..60

    const float* Ap = A + (size_t)(bm + arow) * K + acol;
    const float* Wp = W + (size_t)brow * N + bn + bcol;

    float acc[8][4];
    #pragma unroll
    for (int i = 0; i < 8; i++)
        #pragma unroll
        for (int j = 0; j < 4; j++) acc[i][j] = 0.f;

    for (int k0 = 0; k0 < K; k0 += 16) {
        float4 a0 = *(const float4*)Ap;
        float4 a1 = *(const float4*)(Ap + (size_t)64 * K);
        float4 b0 = *(const float4*)Wp;
        As[acol + 0][arow] = a0.x; As[acol + 1][arow] = a0.y;
        As[acol + 2][arow] = a0.z; As[acol + 3][arow] = a0.w;
        As[acol + 0][arow + 64] = a1.x; As[acol + 1][arow + 64] = a1.y;
        As[acol + 2][arow + 64] = a1.z; As[acol + 3][arow + 64] = a1.w;
        *(float4*)&Bs[brow][bcol] = b0;
        __syncthreads();
        #pragma unroll
        for (int k = 0; k < 16; k++) {
            float a[8], bb[4];
            *(float4*)&a[0] = *(const float4*)&As[k][trow];
            *(float4*)&a[4] = *(const float4*)&As[k][trow + 4];
            *(float4*)&bb[0] = *(const float4*)&Bs[k][tcol];
            #pragma unroll
            for (int i = 0; i < 8; i++)
                #pragma unroll
                for (int j = 0; j < 4; j++)
                    acc[i][j] = fmaf(a[i], bb[j], acc[i][j]);
        }
        __syncthreads();
        Ap += 16;
        Wp += (size_t)16 * N;
    }

    float4 bv = *(const float4*)(bias + bn + tcol);
    #pragma unroll
    for (int i = 0; i < 8; i++) {
        int gr = bm + trow + i;
        float4 r;
        r.x = acc[i][0] + bv.x; r.y = acc[i][1] + bv.y;
        r.z = acc[i][2] + bv.z; r.w = acc[i][3] + bv.w;
        if (EPI == 1) {
            r.x = gelu_exact(r.x); r.y = gelu_exact(r.y);
            r.z = gelu_exact(r.z); r.w = gelu_exact(r.w);
        }
        if (EPI == 0 || EPI == 1) {
            *(float4*)(out + (size_t)gr * N + bn + tcol) = r;
        } else if (EPI == 2) {
            int pix = pix_row(gr, shift);
            float4* p = (float4*)(xbuf + (size_t)pix * CC + bn + tcol);
            float4 old = *p;
            r.x += old.x; r.y += old.y; r.z += old.z; r.w += old.w;
            *p = r;
        } else { // EPI == 3
            float4* p = (float4*)(xbuf + (size_t)gr * CC + bn + tcol);
            float4 old = *p;
            r.x += old.x; r.y += old.y; r.z += old.z; r.w += old.w;
            *p = r;
        }
    }
}

// ---------------- window attention: one block per (window, head) ----------------
__global__ __launch_bounds__(256) void attn_kernel(
    const float* __restrict__ qkv, const float* __restrict__ rpb,
    float* __restrict__ out, int masked)
{
    __shared__ float qs[64][33];
    __shared__ float ks[64][33];
    __shared__ float vs[64][33];
    __shared__ float ss[64][65];
    __shared__ int   lab[64];

    const int win = blockIdx.x;
    const int h   = blockIdx.y;
    const int tid = threadIdx.x;
    const float scale = 0.17677669529663687f;  // 1/sqrt(32)

    // load q,k,v for this (window, head) into smem
    {
        int jr = tid >> 3;            // 0..31
        int d4 = (tid & 7) << 2;      // 0..28
        #pragma unroll
        for (int p = 0; p < 2; p++) {
            int j = jr + p * 32;
            size_t base = (size_t)(win * 64 + j) * 768 + h * 32 + d4;
            float4 q  = *(const float4*)(qkv + base);
            float4 kk = *(const float4*)(qkv + base + 256);
            float4 vv = *(const float4*)(qkv + base + 512);
            qs[j][d4 + 0] = q.x * scale; qs[j][d4 + 1] = q.y * scale;
            qs[j][d4 + 2] = q.z * scale; qs[j][d4 + 3] = q.w * scale;
            ks[j][d4 + 0] = kk.x; ks[j][d4 + 1] = kk.y;
            ks[j][d4 + 2] = kk.z; ks[j][d4 + 3] = kk.w;
            vs[j][d4 + 0] = vv.x; vs[j][d4 + 1] = vv.y;
            vs[j][d4 + 2] = vv.z; vs[j][d4 + 3] = vv.w;
        }
    }
    if (tid < 64) {
        int wi = win & 63;
        int rp = ((wi >> 3) << 3) + (tid >> 3);
        int cp = ((wi & 7) << 3) + (tid & 7);
        int rr = rp < 56 ? 0 : (rp < 60 ? 1 : 2);
        int rc = cp < 56 ? 0 : (cp < 60 ? 1 : 2);
        lab[tid] = rr * 3 + rc;
    }
    __syncthreads();

    const int i  = tid >> 2;         // row 0..63
    const int jb = (tid & 3) << 4;   // col base: 0,16,32,48
    const int ri = i >> 3, ci = i & 7;
    const int li = lab[i];

    float sreg[16];
    #pragma unroll
    for (int jj = 0; jj < 16; jj++) {
        int j = jb + jj;
        float acc = 0.f;
        #pragma unroll
        for (int d = 0; d < 32; d++) acc = fmaf(qs[i][d], ks[j][d], acc);
        int relidx = (ri - (j >> 3) + 7) * 15 + (ci - (j & 7) + 7);
        acc += rpb[relidx * 8 + h];
        if (masked && lab[j] != li) acc -= 100.f;
        sreg[jj] = acc;
    }
    // softmax across the 4 threads of each row (same warp, adjacent lanes)
    float m = sreg[0];
    #pragma unroll
    for (int jj = 1; jj < 16; jj++) m = fmaxf(m, sreg[jj]);
    m = fmaxf(m, __shfl_xor_sync(0xffffffffu, m, 1));
    m = fmaxf(m, __shfl_xor_sync(0xffffffffu, m, 2));
    float sum = 0.f;
    #pragma unroll
    for (int jj = 0; jj < 16; jj++) { sreg[jj] = expf(sreg[jj] - m); sum += sreg[jj]; }
    sum += __shfl_xor_sync(0xffffffffu, sum, 1);
    sum += __shfl_xor_sync(0xffffffffu, sum, 2);
    float inv = 1.f / sum;
    #pragma unroll
    for (int jj = 0; jj < 16; jj++) ss[i][jb + jj] = sreg[jj] * inv;
    __syncthreads();

    // out_i = P_i @ V    (each thread: 8 channels of row i)
    const int db = (tid & 3) << 3;   // 0,8,16,24
    float o[8];
    #pragma unroll
    for (int dd = 0; dd < 8; dd++) o[dd] = 0.f;
    #pragma unroll
    for (int j = 0; j < 64; j++) {
        float p = ss[i][j];
        #pragma unroll
        for (int dd = 0; dd < 8; dd++) o[dd] = fmaf(p, vs[j][db + dd], o[dd]);
    }
    size_t obase = (size_t)(win * 64 + i) * CC + h * 32 + db;
    *(float4*)(out + obase)     = make_float4(o[0], o[1], o[2], o[3]);
    *(float4*)(out + obase + 4) = make_float4(o[4], o[5], o[6], o[7]);
}

// ---------------- launch ----------------
extern "C" void kernel_launch(void* const* d_in, const int* in_sizes, int n_in,
                              void* d_out, int out_size)
{
    const float* x      = (const float*)d_in[0];
    const float* qkv_w  = (const float*)d_in[1];
    const float* qkv_b  = (const float*)d_in[2];
    const float* proj_w = (const float*)d_in[3];
    const float* proj_b = (const float*)d_in[4];
    const float* ln1_g  = (const float*)d_in[5];
    const float* ln1_b  = (const float*)d_in[6];
    const float* ln2_g  = (const float*)d_in[7];
    const float* ln2_b  = (const float*)d_in[8];
    const float* fc1_w  = (const float*)d_in[9];
    const float* fc1_b  = (const float*)d_in[10];
    const float* fc2_w  = (const float*)d_in[11];
    const float* fc2_b  = (const float*)d_in[12];
    const float* rpb    = (const float*)d_in[13];

    float* xbuf = (float*)d_out;   // running x lives in d_out

    float *hw, *qkv, *att, *ln, *mid;
    cudaGetSymbolAddress((void**)&hw,  g_hw);
    cudaGetSymbolAddress((void**)&qkv, g_qkv);
    cudaGetSymbolAddress((void**)&att, g_att);
    cudaGetSymbolAddress((void**)&ln,  g_ln);
    cudaGetSymbolAddress((void**)&mid, g_mid);

    cudaMemcpyAsync(xbuf, x, (size_t)TOK * CC * sizeof(float),
                    cudaMemcpyDeviceToDevice);

    for (int d = 0; d < DEPTH; d++) {
        int shift = d ? 4 : 0;

        // LN1 + shift + window partition
        ln_kernel<<<TOK, 256>>>(xbuf, ln1_g + d * CC, ln1_b + d * CC, hw, 1, shift);

        // qkv: [TOK,256] @ [256,768]
        gemm_kernel<0><<<dim3(12, 256), 256>>>(
            hw, qkv_w + (size_t)d * CC * 3 * CC, qkv_b + (size_t)d * 3 * CC,
            qkv, TOK, 3 * CC, CC, nullptr, 0);

        // window attention (rel-pos bias + optional shift mask + softmax)
        attn_kernel<<<dim3(NWIN, HEADS), 256>>>(qkv, rpb + (size_t)d * 225 * 8, att, d);

        // proj: [TOK,256] @ [256,256], scatter back (reverse+unshift) + residual
        gemm_kernel<2><<<dim3(4, 256), 256>>>(
            att, proj_w + (size_t)d * CC * CC, proj_b + (size_t)d * CC,
            xbuf, TOK, CC, CC, xbuf, shift);

        // LN2
        ln_kernel<<<TOK, 256>>>(xbuf, ln2_g + d * CC, ln2_b + d * CC, ln, 0, 0);

        // fc1 + exact GELU: [TOK,256] @ [256,1024]
        gemm_kernel<1><<<dim3(16, 256), 256>>>(
            ln, fc1_w + (size_t)d * CC * HID, fc1_b + (size_t)d * HID,
            mid, TOK, HID, CC, nullptr, 0);

        // fc2 + residual: [TOK,1024] @ [1024,256]
        gemm_kernel<3><<<dim3(4, 256), 256>>>(
            mid, fc2_w + (size_t)d * HID * CC, fc2_b + (size_t)d * CC,
            xbuf, TOK, CC, HID, xbuf, 0);
    }
}

// round 7
// speedup vs baseline: 2.5563x; 2.5563x over previous
#include <cuda_runtime.h>
#include <cuda_bf16.h>
#include <math.h>
#include <stdint.h>

#define TOK 32768          // B * H * W tokens
#define CC 256             // dim
#define HEADS 8
#define HID 1024
#define NWIN 512           // B * nW windows
#define DEPTH 2

// ---------------- scratch (static device globals; no runtime alloc) ----------------
__device__ __nv_bfloat16 g_hw_bf [TOK * CC];        // LN1 + shifted window partition
__device__ __nv_bfloat16 g_qkv_bf[TOK * 3 * CC];    // qkv activations
__device__ __nv_bfloat16 g_att_bf[TOK * CC];        // attention output (window order)
__device__ __nv_bfloat16 g_ln_bf [TOK * CC];        // LN2 output
__device__ __nv_bfloat16 g_mid_bf[TOK * HID];       // MLP hidden (post-GELU)

// transposed bf16 weights, [N,K] K-major, packed per depth
#define OFF_QKV 0
#define OFF_PROJ 196608
#define OFF_FC1  262144
#define OFF_FC2  524288
#define DEP_STRIDE 786432
__device__ __nv_bfloat16 g_wt[DEP_STRIDE * DEPTH];

// ---------------- helpers ----------------
__device__ __forceinline__ uint32_t smem_u32(const void* p) {
    uint32_t a;
    asm("{ .reg .u64 t; cvta.to.shared.u64 t, %1; cvt.u32.u64 %0, t; }" : "=r"(a) : "l"(p));
    return a;
}

// window-token row t  ->  source/dest pixel row (shift applied mod 64)
__device__ __forceinline__ int pix_row(int t, int shift) {
    int win = t >> 6, tok = t & 63;
    int b = win >> 6, wi = win & 63;
    int rp = ((wi >> 3) << 3) + (tok >> 3);
    int cp = ((wi & 7) << 3) + (tok & 7);
    int r = (rp + shift) & 63;
    int c = (cp + shift) & 63;
    return (b << 12) + (r << 6) + c;
}

__device__ __forceinline__ float gelu_exact(float x) {
    return 0.5f * x * (1.0f + erff(x * 0.7071067811865476f));
}

__device__ __forceinline__ uint32_t pack_bf2(float a, float b) {
    __nv_bfloat162 h = __floats2bfloat162_rn(a, b);
    return *reinterpret_cast<uint32_t*>(&h);
}

__device__ __forceinline__ void ldm_x4(uint32_t* r, uint32_t addr) {
    asm volatile("ldmatrix.sync.aligned.m8n8.x4.shared.b16 {%0,%1,%2,%3}, [%4];"
                 : "=r"(r[0]), "=r"(r[1]), "=r"(r[2]), "=r"(r[3]) : "r"(addr));
}

__device__ __forceinline__ void mma_bf16(float* c, const uint32_t* a, const uint32_t* b) {
    asm volatile(
        "mma.sync.aligned.m16n8k16.row.col.f32.bf16.bf16.f32 "
        "{%0,%1,%2,%3}, {%4,%5,%6,%7}, {%8,%9}, {%0,%1,%2,%3};"
        : "+f"(c[0]), "+f"(c[1]), "+f"(c[2]), "+f"(c[3])
        : "r"(a[0]), "r"(a[1]), "r"(a[2]), "r"(a[3]), "r"(b[0]), "r"(b[1]));
}

// ---------------- weight transpose + bf16 convert: w[K,N] -> wt[N,K] ----------------
__global__ __launch_bounds__(256) void transpose_bf16(
    const float* __restrict__ w, __nv_bfloat16* __restrict__ wt, int K, int N)
{
    __shared__ float t[32][33];
    int nb = blockIdx.x << 5, kb = blockIdx.y << 5;
    int tx = threadIdx.x & 31, ty = threadIdx.x >> 5;  // 32 x 8
    #pragma unroll
    for (int i = ty; i < 32; i += 8)
        t[i][tx] = w[(size_t)(kb + i) * N + nb + tx];
    __syncthreads();
    #pragma unroll
    for (int i = ty; i < 32; i += 8)
        wt[(size_t)(nb + i) * K + kb + tx] = __float2bfloat16(t[tx][i]);
}

// ---------------- LayerNorm (optionally fused shift + window partition), bf16 out ----
__global__ __launch_bounds__(256) void ln_kernel(
    const float* __restrict__ in, const float* __restrict__ g,
    const float* __restrict__ b, __nv_bfloat16* __restrict__ out,
    int permute, int shift)
{
    int row = blockIdx.x;
    int src = permute ? pix_row(row, shift) : row;
    int ch = threadIdx.x;
    float v = in[(size_t)src * CC + ch];

    float s = v, s2 = v * v;
    #pragma unroll
    for (int o = 16; o; o >>= 1) {
        s  += __shfl_xor_sync(0xffffffffu, s,  o);
        s2 += __shfl_xor_sync(0xffffffffu, s2, o);
    }
    __shared__ float ws[8], ws2[8];
    int w = ch >> 5, l = ch & 31;
    if (l == 0) { ws[w] = s; ws2[w] = s2; }
    __syncthreads();
    float ts = 0.f, ts2 = 0.f;
    #pragma unroll
    for (int i = 0; i < 8; i++) { ts += ws[i]; ts2 += ws2[i]; }
    float mu  = ts * (1.0f / CC);
    float var = ts2 * (1.0f / CC) - mu * mu;
    float inv = rsqrtf(var + 1e-5f);
    out[(size_t)row * CC + ch] =
        __float2bfloat16((v - mu) * inv * g[ch] + b[ch]);
}

// ---------------- HMMA bf16 GEMM: 128x128 tile, BK=64, 2-stage double buffer -------
// out[M,N] = A[M,K] @ Wt[N,K]^T + bias, both operands K-major.
// EPI 0: store bf16   EPI 1: GELU + store bf16
// EPI 2: scatter (window-reverse+unshift) + residual fp32   EPI 3: residual fp32
#define STAGE_BYTES 32768            // 16KB A + 16KB B
#define GEMM_SMEM   (2 * STAGE_BYTES)

// swizzled smem byte offset for (row, 16B-seg)
#define SWZ(row, seg) ((uint32_t)((row) * 128 + ((((seg) ^ ((row) & 7))) << 4)))

template<int EPI>
__global__ __launch_bounds__(256, 1)
void mma_gemm(const __nv_bfloat16* __restrict__ A, const __nv_bfloat16* __restrict__ Wt,
              const float* __restrict__ bias, __nv_bfloat16* __restrict__ out,
              int M, int N, int K, float* __restrict__ xbuf, int shift)
{
    extern __shared__ char sm[];
    const uint32_t smb = smem_u32(sm);

    const int tid  = threadIdx.x;
    const int lane = tid & 31;
    const int wid  = tid >> 5;
    const int wm   = wid >> 2;        // 0..1  (M)
    const int wn   = wid & 3;         // 0..3  (N)
    const int bm   = blockIdx.y << 7;
    const int bn   = blockIdx.x << 7;
    const int NC   = K >> 6;

    const __nv_bfloat16* Abase = A  + (size_t)bm * K;
    const __nv_bfloat16* Bbase = Wt + (size_t)bn * K;

    float acc[4][4][4];
    #pragma unroll
    for (int i = 0; i < 4; i++)
        #pragma unroll
        for (int j = 0; j < 4; j++)
            #pragma unroll
            for (int q = 0; q < 4; q++) acc[i][j][q] = 0.f;

    // gmem<->smem mapping: idx = i*256 + tid -> row = idx>>3, seg = idx&7 (16B)
    uint4 pa[4], pb[4];
    #pragma unroll
    for (int i = 0; i < 4; i++) {
        int idx = i * 256 + tid, r = idx >> 3, sg = idx & 7;
        pa[i] = *(const uint4*)(Abase + (size_t)r * K + sg * 8);
        pb[i] = *(const uint4*)(Bbase + (size_t)r * K + sg * 8);
    }
    #pragma unroll
    for (int i = 0; i < 4; i++) {
        int idx = i * 256 + tid, r = idx >> 3, sg = idx & 7;
        *(uint4*)(sm + SWZ(r, sg))         = pa[i];
        *(uint4*)(sm + 16384 + SWZ(r, sg)) = pb[i];
    }
    __syncthreads();

    // per-lane ldmatrix row components (fixed across chunks)
    const int arow = wm * 64 + (lane & 7) + ((lane >> 3) & 1) * 8;  // + mt*16
    const int asegl = lane >> 4;                                     // + 2*k16
    const int brow = wn * 32 + ((lane >> 4) << 3) + (lane & 7);      // + p*16
    const int bsegl = (lane >> 3) & 1;                               // + 2*k16

    for (int c = 0; c < NC; ++c) {
        const int s = c & 1;
        if (c + 1 < NC) {
            const __nv_bfloat16* ap = Abase + (c + 1) * 64;
            const __nv_bfloat16* bp = Bbase + (c + 1) * 64;
            #pragma unroll
            for (int i = 0; i < 4; i++) {
                int idx = i * 256 + tid, r = idx >> 3, sg = idx & 7;
                pa[i] = *(const uint4*)(ap + (size_t)r * K + sg * 8);
                pb[i] = *(const uint4*)(bp + (size_t)r * K + sg * 8);
            }
        }

        const uint32_t Aoff = smb + s * STAGE_BYTES;
        const uint32_t Boff = Aoff + 16384;

        #pragma unroll
        for (int k16 = 0; k16 < 4; ++k16) {
            uint32_t af[4][4];
            #pragma unroll
            for (int mt = 0; mt < 4; ++mt) {
                int row = arow + mt * 16;
                int seg = 2 * k16 + asegl;
                ldm_x4(af[mt], Aoff + SWZ(row, seg));
            }
            uint32_t bfr[4][2];
            #pragma unroll
            for (int p = 0; p < 2; ++p) {
                uint32_t r4[4];
                int row = brow + p * 16;
                int seg = 2 * k16 + bsegl;
                ldm_x4(r4, Boff + SWZ(row, seg));
                bfr[2*p][0] = r4[0]; bfr[2*p][1] = r4[1];
                bfr[2*p+1][0] = r4[2]; bfr[2*p+1][1] = r4[3];
            }
            #pragma unroll
            for (int mt = 0; mt < 4; ++mt)
                #pragma unroll
                for (int nt = 0; nt < 4; ++nt)
                    mma_bf16(acc[mt][nt], af[mt], bfr[nt]);
        }

        if (c + 1 < NC) {
            __syncthreads();
            char* dst = sm + (s ^ 1) * STAGE_BYTES;
            #pragma unroll
            for (int i = 0; i < 4; i++) {
                int idx = i * 256 + tid, r = idx >> 3, sg = idx & 7;
                *(uint4*)(dst + SWZ(r, sg))         = pa[i];
                *(uint4*)(dst + 16384 + SWZ(r, sg)) = pb[i];
            }
            __syncthreads();
        }
    }

    // ---------------- epilogue ----------------
    // acc[mt][nt]: c0,c1 -> row r0 = lane>>2, cols (lane&3)*2,+1 ; c2,c3 -> r0+8
    const int colb = bn + wn * 32 + (lane & 3) * 2;
    #pragma unroll
    for (int mt = 0; mt < 4; ++mt) {
        int r0 = bm + wm * 64 + mt * 16 + (lane >> 2);
        int r1 = r0 + 8;
        if (EPI == 0 || EPI == 1) {
            __nv_bfloat16* o0 = out + (size_t)r0 * N;
            __nv_bfloat16* o1 = out + (size_t)r1 * N;
            #pragma unroll
            for (int nt = 0; nt < 4; ++nt) {
                int col = colb + nt * 8;
                float2 bv = *(const float2*)(bias + col);
                float v0 = acc[mt][nt][0] + bv.x;
                float v1 = acc[mt][nt][1] + bv.y;
                float v2 = acc[mt][nt][2] + bv.x;
                float v3 = acc[mt][nt][3] + bv.y;
                if (EPI == 1) {
                    v0 = gelu_exact(v0); v1 = gelu_exact(v1);
                    v2 = gelu_exact(v2); v3 = gelu_exact(v3);
                }
                *(uint32_t*)(o0 + col) = pack_bf2(v0, v1);
                *(uint32_t*)(o1 + col) = pack_bf2(v2, v3);
            }
        } else {
            int p0 = (EPI == 2) ? pix_row(r0, shift) : r0;
            int p1 = (EPI == 2) ? pix_row(r1, shift) : r1;
            float* x0 = xbuf + (size_t)p0 * CC;
            float* x1 = xbuf + (size_t)p1 * CC;
            #pragma unroll
            for (int nt = 0; nt < 4; ++nt) {
                int col = colb + nt * 8;
                float2 bv = *(const float2*)(bias + col);
                float2 o0 = *(float2*)(x0 + col);
                float2 o1 = *(float2*)(x1 + col);
                o0.x += acc[mt][nt][0] + bv.x;
                o0.y += acc[mt][nt][1] + bv.y;
                o1.x += acc[mt][nt][2] + bv.x;
                o1.y += acc[mt][nt][3] + bv.y;
                *(float2*)(x0 + col) = o0;
                *(float2*)(x1 + col) = o1;
            }
        }
    }
}

// ---------------- window attention: one block per (window, head), bf16 I/O ----------
__global__ __launch_bounds__(256) void attn_kernel(
    const __nv_bfloat16* __restrict__ qkv, const float* __restrict__ rpb,
    __nv_bfloat16* __restrict__ out, int masked)
{
    __shared__ float qs[64][33];
    __shared__ float ks[64][33];
    __shared__ float vs[64][33];
    __shared__ float ss[64][65];
    __shared__ int   lab[64];

    const int win = blockIdx.x;
    const int h   = blockIdx.y;
    const int tid = threadIdx.x;
    const float scale = 0.17677669529663687f;  // 1/sqrt(32)

    {
        int j  = tid >> 2;            // 0..63
        int d8 = (tid & 3) << 3;      // 0,8,16,24
        size_t bofs = (size_t)(win * 64 + j) * 768 + h * 32 + d8;
        uint4 uq = *(const uint4*)(qkv + bofs);
        uint4 uk = *(const uint4*)(qkv + bofs + 256);
        uint4 uv = *(const uint4*)(qkv + bofs + 512);
        const __nv_bfloat162* hq = (const __nv_bfloat162*)&uq;
        const __nv_bfloat162* hk = (const __nv_bfloat162*)&uk;
        const __nv_bfloat162* hv = (const __nv_bfloat162*)&uv;
        #pragma unroll
        for (int p = 0; p < 4; ++p) {
            float2 fq = __bfloat1622float2(hq[p]);
            float2 fk = __bfloat1622float2(hk[p]);
            float2 fv = __bfloat1622float2(hv[p]);
            qs[j][d8 + p*2 + 0] = fq.x * scale; qs[j][d8 + p*2 + 1] = fq.y * scale;
            ks[j][d8 + p*2 + 0] = fk.x;         ks[j][d8 + p*2 + 1] = fk.y;
            vs[j][d8 + p*2 + 0] = fv.x;         vs[j][d8 + p*2 + 1] = fv.y;
        }
    }
    if (tid < 64) {
        int wi = win & 63;
        int rp = ((wi >> 3) << 3) + (tid >> 3);
        int cp = ((wi & 7) << 3) + (tid & 7);
        int rr = rp < 56 ? 0 : (rp < 60 ? 1 : 2);
        int rc = cp < 56 ? 0 : (cp < 60 ? 1 : 2);
        lab[tid] = rr * 3 + rc;
    }
    __syncthreads();

    const int i  = tid >> 2;         // row 0..63
    const int jb = (tid & 3) << 4;   // col base: 0,16,32,48
    const int ri = i >> 3, ci = i & 7;
    const int li = lab[i];

    float sreg[16];
    #pragma unroll
    for (int jj = 0; jj < 16; jj++) {
        int j = jb + jj;
        float acc = 0.f;
        #pragma unroll
        for (int d = 0; d < 32; d++) acc = fmaf(qs[i][d], ks[j][d], acc);
        int relidx = (ri - (j >> 3) + 7) * 15 + (ci - (j & 7) + 7);
        acc += rpb[relidx * 8 + h];
        if (masked && lab[j] != li) acc -= 100.f;
        sreg[jj] = acc;
    }
    float m = sreg[0];
    #pragma unroll
    for (int jj = 1; jj < 16; jj++) m = fmaxf(m, sreg[jj]);
    m = fmaxf(m, __shfl_xor_sync(0xffffffffu, m, 1));
    m = fmaxf(m, __shfl_xor_sync(0xffffffffu, m, 2));
    float sum = 0.f;
    #pragma unroll
    for (int jj = 0; jj < 16; jj++) { sreg[jj] = expf(sreg[jj] - m); sum += sreg[jj]; }
    sum += __shfl_xor_sync(0xffffffffu, sum, 1);
    sum += __shfl_xor_sync(0xffffffffu, sum, 2);
    float inv = 1.f / sum;
    #pragma unroll
    for (int jj = 0; jj < 16; jj++) ss[i][jb + jj] = sreg[jj] * inv;
    __syncthreads();

    const int db = (tid & 3) << 3;   // 0,8,16,24
    float o[8];
    #pragma unroll
    for (int dd = 0; dd < 8; dd++) o[dd] = 0.f;
    #pragma unroll
    for (int j = 0; j < 64; j++) {
        float p = ss[i][j];
        #pragma unroll
        for (int dd = 0; dd < 8; dd++) o[dd] = fmaf(p, vs[j][db + dd], o[dd]);
    }
    size_t obase = (size_t)(win * 64 + i) * CC + h * 32 + db;
    uint4 u;
    u.x = pack_bf2(o[0], o[1]); u.y = pack_bf2(o[2], o[3]);
    u.z = pack_bf2(o[4], o[5]); u.w = pack_bf2(o[6], o[7]);
    *(uint4*)(out + obase) = u;
}

// ---------------- launch ----------------
extern "C" void kernel_launch(void* const* d_in, const int* in_sizes, int n_in,
                              void* d_out, int out_size)
{
    const float* x      = (const float*)d_in[0];
    const float* qkv_w  = (const float*)d_in[1];
    const float* qkv_b  = (const float*)d_in[2];
    const float* proj_w = (const float*)d_in[3];
    const float* proj_b = (const float*)d_in[4];
    const float* ln1_g  = (const float*)d_in[5];
    const float* ln1_b  = (const float*)d_in[6];
    const float* ln2_g  = (const float*)d_in[7];
    const float* ln2_b  = (const float*)d_in[8];
    const float* fc1_w  = (const float*)d_in[9];
    const float* fc1_b  = (const float*)d_in[10];
    const float* fc2_w  = (const float*)d_in[11];
    const float* fc2_b  = (const float*)d_in[12];
    const float* rpb    = (const float*)d_in[13];

    float* xbuf = (float*)d_out;   // running x lives in d_out

    __nv_bfloat16 *hw, *qkv, *att, *ln, *mid, *wt;
    cudaGetSymbolAddress((void**)&hw,  g_hw_bf);
    cudaGetSymbolAddress((void**)&qkv, g_qkv_bf);
    cudaGetSymbolAddress((void**)&att, g_att_bf);
    cudaGetSymbolAddress((void**)&ln,  g_ln_bf);
    cudaGetSymbolAddress((void**)&mid, g_mid_bf);
    cudaGetSymbolAddress((void**)&wt,  g_wt);

    cudaFuncSetAttribute(mma_gemm<0>, cudaFuncAttributeMaxDynamicSharedMemorySize, GEMM_SMEM);
    cudaFuncSetAttribute(mma_gemm<1>, cudaFuncAttributeMaxDynamicSharedMemorySize, GEMM_SMEM);
    cudaFuncSetAttribute(mma_gemm<2>, cudaFuncAttributeMaxDynamicSharedMemorySize, GEMM_SMEM);
    cudaFuncSetAttribute(mma_gemm<3>, cudaFuncAttributeMaxDynamicSharedMemorySize, GEMM_SMEM);

    cudaMemcpyAsync(xbuf, x, (size_t)TOK * CC * sizeof(float),
                    cudaMemcpyDeviceToDevice);

    // weight transpose + bf16 convert (per depth)
    for (int d = 0; d < DEPTH; d++) {
        __nv_bfloat16* wd = wt + (size_t)d * DEP_STRIDE;
        transpose_bf16<<<dim3(24, 8),  256>>>(qkv_w  + (size_t)d * CC * 3 * CC, wd + OFF_QKV, CC, 3 * CC);
        transpose_bf16<<<dim3(8, 8),   256>>>(proj_w + (size_t)d * CC * CC,     wd + OFF_PROJ, CC, CC);
        transpose_bf16<<<dim3(32, 8),  256>>>(fc1_w  + (size_t)d * CC * HID,    wd + OFF_FC1, CC, HID);
        transpose_bf16<<<dim3(8, 32),  256>>>(fc2_w  + (size_t)d * HID * CC,    wd + OFF_FC2, HID, CC);
    }

    for (int d = 0; d < DEPTH; d++) {
        int shift = d ? 4 : 0;
        __nv_bfloat16* wd = wt + (size_t)d * DEP_STRIDE;

        // LN1 + shift + window partition -> bf16
        ln_kernel<<<TOK, 256>>>(xbuf, ln1_g + d * CC, ln1_b + d * CC, hw, 1, shift);

        // qkv: [TOK,256] @ [256,768] -> bf16
        mma_gemm<0><<<dim3(6, 256), 256, GEMM_SMEM>>>(
            hw, wd + OFF_QKV, qkv_b + (size_t)d * 3 * CC, qkv,
            TOK, 3 * CC, CC, nullptr, 0);

        // window attention
        attn_kernel<<<dim3(NWIN, HEADS), 256>>>(qkv, rpb + (size_t)d * 225 * 8, att, d);

        // proj + scatter (reverse+unshift) + residual (fp32 xbuf)
        mma_gemm<2><<<dim3(2, 256), 256, GEMM_SMEM>>>(
            att, wd + OFF_PROJ, proj_b + (size_t)d * CC, nullptr,
            TOK, CC, CC, xbuf, shift);

        // LN2 -> bf16
        ln_kernel<<<TOK, 256>>>(xbuf, ln2_g + d * CC, ln2_b + d * CC, ln, 0, 0);

        // fc1 + exact GELU -> bf16
        mma_gemm<1><<<dim3(8, 256), 256, GEMM_SMEM>>>(
            ln, wd + OFF_FC1, fc1_b + (size_t)d * HID, mid,
            TOK, HID, CC, nullptr, 0);

        // fc2 + residual (fp32 xbuf)
        mma_gemm<3><<<dim3(2, 256), 256, GEMM_SMEM>>>(
            mid, wd + OFF_FC2, fc2_b + (size_t)d * CC, nullptr,
            TOK, CC, HID, xbuf, 0);
    }
}